// round 17
// baseline (speedup 1.0000x reference)
#include <cuda_runtime.h>
#include <cstdint>

#define D 1024
#define H 8
#define RPW 4                      // rows per warp
#define RPB 32                     // rows per chunk == warp size
#define NCH 8                      // column chunks (1024/128)
#define MAXCHUNK 512
#define NEG_INF (-3.402823466e38f)

// fallback-only scratch
__device__ float g_e[16384 * H];
// decoupled-lookback state: per-chunk aggregate / inclusive prefix maps
__device__ float    g_agg [MAXCHUNK][3][H];
__device__ float    g_pref[MAXCHUNK][3][H];
__device__ unsigned g_st  [MAXCHUNK];     // 3*epoch+1 = AGG ready, 3*epoch+2 = PREFIX ready
__device__ unsigned g_tick;               // monotone launch counter (epoch source)
__device__ unsigned g_done;               // fallback completion counter

// ---------------------------------------------------------------------------
// Single fused kernel: skinny GEMM (R4-exact 25.0us config: W in smem, plain
// LDG, 8 warps x 4 rows) + per-chunk aggregate + CUB-style decoupled lookback
// + in-place apply scan + output projection. ONE launch, no g_e round-trip.
// Epoch tags (g_tick/gridDim) make the flag protocol safe across CUDA-graph
// replays without host-side resets.
// ---------------------------------------------------------------------------
__global__ __launch_bounds__(256, 2)
void rnn_fused(const float* __restrict__ x,
               const float* __restrict__ W_ih,
               const float* __restrict__ b_ih,
               const float* __restrict__ W_hh,
               const float* __restrict__ b_hh,
               const float* __restrict__ W_out,
               const float* __restrict__ b_out,
               float* __restrict__ out, int T) {
    __shared__ float4   sW[H * (D / 4)];   // 32KB
    __shared__ float    se[RPB][H];
    __shared__ float    sb[H];
    __shared__ unsigned sEp;
    __shared__ int      sBad;

    int tid  = threadIdx.x;
    int warp = tid >> 5, lane = tid & 31;
    int cg   = blockIdx.x;                 // this block's chunk
    int row0 = cg * RPB;

    for (int i = tid; i < H * (D / 4); i += 256)
        sW[i] = ((const float4*)W_ih)[i];
    if (tid < H) sb[tid] = b_ih[tid] + b_hh[tid];
    if (tid == 0) {
        unsigned tick = atomicAdd(&g_tick, 1u);
        sEp = tick / gridDim.x;            // same value for every block of a launch
        int bad = 0;
        for (int i = 0; i < H; i++)
            for (int j = 0; j < H; j++)
                if (i != j && W_hh[i * H + j] != 0.f) bad = 1;
        for (int i = 0; i < H; i++)
            if (!(W_hh[i * H + i] >= 0.f)) bad = 1;
        sBad = bad;
    }
    __syncthreads();

    unsigned ep3 = sEp * 3u;

    // ---- compute e for this chunk (R4-exact inner loop) ----
    const float4* xr = (const float4*)(x + (size_t)(row0 + warp * RPW) * D);
    float acc[RPW][H];
#pragma unroll
    for (int r = 0; r < RPW; r++)
#pragma unroll
        for (int j = 0; j < H; j++) acc[r][j] = 0.f;

#pragma unroll
    for (int i = 0; i < NCH; i++) {
        int col = lane + i * 32;
        float4 xv[RPW];
#pragma unroll
        for (int r = 0; r < RPW; r++) xv[r] = xr[r * (D / 4) + col];
#pragma unroll
        for (int j = 0; j < H; j++) {
            float4 wv = sW[j * (D / 4) + col];
#pragma unroll
            for (int r = 0; r < RPW; r++)
                acc[r][j] += xv[r].x * wv.x + xv[r].y * wv.y +
                             xv[r].z * wv.z + xv[r].w * wv.w;
        }
    }

#pragma unroll
    for (int r = 0; r < RPW; r++)
#pragma unroll
        for (int j = 0; j < H; j++)
#pragma unroll
            for (int o = 16; o > 0; o >>= 1)
                acc[r][j] += __shfl_xor_sync(0xffffffffu, acc[r][j], o);

    if (lane == 0) {
#pragma unroll
        for (int r = 0; r < RPW; r++) {
            int lr = warp * RPW + r;
#pragma unroll
            for (int j = 0; j < H; j++) se[lr][j] = acc[r][j] + sb[j];
        }
    }
    __syncthreads();

    // ---- fallback path (never taken for identity W_hh) ----
    if (sBad) {
        for (int q = tid; q < RPB * H; q += 256) {
            int r = q / H, j = q % H;
            int row = row0 + r;
            if (row < T) g_e[(size_t)row * H + j] = se[r][j];
        }
        __syncthreads();
        if (tid == 0) { __threadfence(); atomicAdd(&g_done, 1u); }
        if (cg == 0 && tid == 0) {
            unsigned target = (sEp + 1u) * gridDim.x;
            while (*(volatile unsigned*)&g_done < target) {}
            __threadfence();
            float h[H], Whh[H * H], wout[H];
            for (int i = 0; i < H * H; i++) Whh[i] = W_hh[i];
            for (int j = 0; j < H; j++) { h[j] = 0.f; wout[j] = W_out[j]; }
            float bo = b_out[0];
            for (int t = 0; t < T; t++) {
                float hn[H];
                for (int j = 0; j < H; j++) {
                    float s = g_e[(size_t)t * H + j];
                    for (int k = 0; k < H; k++) s += Whh[j * H + k] * h[k];
                    hn[j] = fmaxf(s, 0.f);
                }
                float o = bo;
                for (int j = 0; j < H; j++) { h[j] = hn[j]; o += h[j] * wout[j]; }
                out[t] = o;
            }
        }
        return;
    }

    // ---- everything below runs on warp 0 only ----
    if (warp != 0) return;

    float dj[H];
#pragma unroll
    for (int j = 0; j < H; j++) dj[j] = W_hh[j * H + j];

    // own chunk aggregate: every lane computes all H channels redundantly
    float ac[H], aa[H], ab[H];
#pragma unroll
    for (int j = 0; j < H; j++) { ac[j] = 1.f; aa[j] = 0.f; ab[j] = NEG_INF; }
#pragma unroll
    for (int r = 0; r < RPB; r++) {
#pragma unroll
        for (int j = 0; j < H; j++) {
            float e = se[r][j];
            ac[j] = dj[j] * ac[j];
            aa[j] = dj[j] * aa[j] + e;
            ab[j] = fmaxf(dj[j] * ab[j] + e, 0.f);
        }
    }

    // publish AGG: lanes 0..5 store one float4 each, then fence + flag
    {
        float4 pk[6];
        pk[0] = make_float4(ac[0], ac[1], ac[2], ac[3]);
        pk[1] = make_float4(ac[4], ac[5], ac[6], ac[7]);
        pk[2] = make_float4(aa[0], aa[1], aa[2], aa[3]);
        pk[3] = make_float4(aa[4], aa[5], aa[6], aa[7]);
        pk[4] = make_float4(ab[0], ab[1], ab[2], ab[3]);
        pk[5] = make_float4(ab[4], ab[5], ab[6], ab[7]);
        if (lane < 6) ((float4*)&g_agg[cg][0][0])[lane] = pk[lane];
        __syncwarp();
        __threadfence();
        if (lane == 0) *(volatile unsigned*)&g_st[cg] = ep3 + 1u;
    }

    // ---- decoupled lookback: exclusive prefix map (sc,sa,sbf) ----
    float sc[H], sa[H], sbf[H];
#pragma unroll
    for (int j = 0; j < H; j++) { sc[j] = 1.f; sa[j] = 0.f; sbf[j] = NEG_INF; }

    int p = cg - 1;
    while (p >= 0) {
        int idx = p - lane;
        bool active = idx >= 0;
        unsigned tag = 0;
        if (active)
            do { tag = *(volatile unsigned*)&g_st[idx]; } while (tag < ep3 + 1u);
        bool isPre = active && (tag >= ep3 + 2u);
        unsigned bal = __ballot_sync(0xffffffffu, isPre);
        int L = bal ? (__ffs(bal) - 1) : 32;
        bool incl = active && (lane <= L);
        __threadfence();   // acquire: flag observed -> payload reads below

        float bc[H], ba[H], bb[H];
        if (incl) {
            const float4* src = (lane == L) ? (const float4*)&g_pref[idx][0][0]
                                            : (const float4*)&g_agg [idx][0][0];
            float4 v0 = __ldcg(src + 0), v1 = __ldcg(src + 1), v2 = __ldcg(src + 2);
            float4 v3 = __ldcg(src + 3), v4 = __ldcg(src + 4), v5 = __ldcg(src + 5);
            bc[0]=v0.x; bc[1]=v0.y; bc[2]=v0.z; bc[3]=v0.w;
            bc[4]=v1.x; bc[5]=v1.y; bc[6]=v1.z; bc[7]=v1.w;
            ba[0]=v2.x; ba[1]=v2.y; ba[2]=v2.z; ba[3]=v2.w;
            ba[4]=v3.x; ba[5]=v3.y; ba[6]=v3.z; ba[7]=v3.w;
            bb[0]=v4.x; bb[1]=v4.y; bb[2]=v4.z; bb[3]=v4.w;
            bb[4]=v5.x; bb[5]=v5.y; bb[6]=v5.z; bb[7]=v5.w;
        } else {
#pragma unroll
            for (int j = 0; j < H; j++) { bc[j] = 1.f; ba[j] = 0.f; bb[j] = NEG_INF; }
        }

        // reversed inclusive scan: lane l composes lanes l..31 (higher lane = earlier)
#pragma unroll
        for (int off = 1; off < 32; off <<= 1) {
#pragma unroll
            for (int j = 0; j < H; j++) {
                float ec = __shfl_down_sync(0xffffffffu, bc[j], off);
                float ea = __shfl_down_sync(0xffffffffu, ba[j], off);
                float eb = __shfl_down_sync(0xffffffffu, bb[j], off);
                if (lane + off < 32) {
                    bb[j] = fmaxf(bc[j] * eb + ba[j], bb[j]);
                    ba[j] = bc[j] * ea + ba[j];
                    bc[j] = bc[j] * ec;
                }
            }
        }
        // lane0 holds the batch map; broadcast and fold: suf = compose(batch, suf)
#pragma unroll
        for (int j = 0; j < H; j++) {
            float qc = __shfl_sync(0xffffffffu, bc[j], 0);
            float qa = __shfl_sync(0xffffffffu, ba[j], 0);
            float qb = __shfl_sync(0xffffffffu, bb[j], 0);
            sbf[j] = fmaxf(sc[j] * qb + sa[j], sbf[j]);
            sa[j]  = sc[j] * qa + sa[j];
            sc[j]  = sc[j] * qc;
        }
        if (L < 32) break;     // hit a PREFIX -> exclusive map complete
        p -= 32;
    }

    // publish inclusive PREFIX = compose(exclusive, own agg)
    {
        float ic[H], ia[H], ib[H];
#pragma unroll
        for (int j = 0; j < H; j++) {
            ib[j] = fmaxf(ac[j] * sbf[j] + aa[j], ab[j]);
            ia[j] = ac[j] * sa[j] + aa[j];
            ic[j] = ac[j] * sc[j];
        }
        float4 pk[6];
        pk[0] = make_float4(ic[0], ic[1], ic[2], ic[3]);
        pk[1] = make_float4(ic[4], ic[5], ic[6], ic[7]);
        pk[2] = make_float4(ia[0], ia[1], ia[2], ia[3]);
        pk[3] = make_float4(ia[4], ia[5], ia[6], ia[7]);
        pk[4] = make_float4(ib[0], ib[1], ib[2], ib[3]);
        pk[5] = make_float4(ib[4], ib[5], ib[6], ib[7]);
        if (lane < 6) ((float4*)&g_pref[cg][0][0])[lane] = pk[lane];
        __syncwarp();
        __threadfence();
        if (lane == 0) *(volatile unsigned*)&g_st[cg] = ep3 + 2u;
    }

    // ---- apply: lane = timestep within chunk; seed h_in = exclusive(h0=0) ----
    float h_in[H];
#pragma unroll
    for (int j = 0; j < H; j++) h_in[j] = fmaxf(sa[j], sbf[j]);

    int t = row0 + lane;
    bool valid = t < T;
    float c[H], a[H], b[H];
    if (valid) {
#pragma unroll
        for (int j = 0; j < H; j++) { c[j] = dj[j]; a[j] = se[lane][j]; b[j] = 0.f; }
    } else {
#pragma unroll
        for (int j = 0; j < H; j++) { c[j] = 1.f; a[j] = 0.f; b[j] = NEG_INF; }
    }

#pragma unroll
    for (int off = 1; off < 32; off <<= 1) {
#pragma unroll
        for (int j = 0; j < H; j++) {
            float lc = __shfl_up_sync(0xffffffffu, c[j], off);
            float la = __shfl_up_sync(0xffffffffu, a[j], off);
            float lb = __shfl_up_sync(0xffffffffu, b[j], off);
            if (lane >= off) {
                b[j] = fmaxf(c[j] * lb + a[j], b[j]);
                a[j] = c[j] * la + a[j];
                c[j] = c[j] * lc;
            }
        }
    }

    if (valid) {
        float o = b_out[0];
#pragma unroll
        for (int j = 0; j < H; j++) {
            float h = fmaxf(c[j] * h_in[j] + a[j], b[j]);
            o += h * W_out[j];
        }
        out[t] = o;
    }
}

// ---------------------------------------------------------------------------
// inputs: 0:x [1,T,1024] 1:W_ih[8,1024] 2:b_ih[8] 3:W_hh[8,8] 4:b_hh[8]
//         5:W_out[1,8]   6:b_out[1]      output: [1,T,1] f32
// ---------------------------------------------------------------------------
extern "C" void kernel_launch(void* const* d_in, const int* in_sizes, int n_in,
                              void* d_out, int out_size) {
    const float* x     = (const float*)d_in[0];
    const float* W_ih  = (const float*)d_in[1];
    const float* b_ih  = (const float*)d_in[2];
    const float* W_hh  = (const float*)d_in[3];
    const float* b_hh  = (const float*)d_in[4];
    const float* W_out = (const float*)d_in[5];
    const float* b_out = (const float*)d_in[6];
    float* out = (float*)d_out;

    int T = in_sizes[0] / D;                 // 16384
    int nchunk = (T + RPB - 1) / RPB;        // 512

    rnn_fused<<<nchunk, 256>>>(x, W_ih, b_ih, W_hh, b_hh, W_out, b_out, out, T);
}